// round 6
// baseline (speedup 1.0000x reference)
#include <cuda_runtime.h>
#include <cuda_bf16.h>
#include <math.h>
#include <stdint.h>

// Problem constants
#define Bn  2
#define Tn  2048
#define Cn  1024
#define Hn  16
#define HDn 64
#define QKV_N (3*Cn)          // 3072
#define Mrows (Bn*Tn)         // 4096

// Scratch (allocation-free: __device__ globals)
__device__ float g_qkv[(size_t)Mrows * QKV_N];
__device__ __nv_bfloat16 g_xhi[(size_t)Mrows * Cn];
__device__ __nv_bfloat16 g_xlo[(size_t)Mrows * Cn];
__device__ __nv_bfloat16 g_wahi[(size_t)Cn * QKV_N];
__device__ __nv_bfloat16 g_walo[(size_t)Cn * QKV_N];
__device__ __nv_bfloat16 g_wphi[(size_t)Cn * Cn];
__device__ __nv_bfloat16 g_wplo[(size_t)Cn * Cn];
__device__ __nv_bfloat16 g_yhi[(size_t)Mrows * Cn];
__device__ __nv_bfloat16 g_ylo[(size_t)Mrows * Cn];

// ===========================================================================
// fp32 -> bf16 hi/lo split (elementwise, vectorized)
// ===========================================================================
__global__ __launch_bounds__(256)
void split_kernel(const float* __restrict__ src, __nv_bfloat16* __restrict__ hi,
                  __nv_bfloat16* __restrict__ lo, int n4)
{
    int i = blockIdx.x * blockDim.x + threadIdx.x;
    if (i >= n4) return;
    float4 v = ((const float4*)src)[i];
    __nv_bfloat16 hx = __float2bfloat16(v.x), hy = __float2bfloat16(v.y);
    __nv_bfloat16 hz = __float2bfloat16(v.z), hw = __float2bfloat16(v.w);
    ((__nv_bfloat162*)hi)[2 * i]     = __nv_bfloat162(hx, hy);
    ((__nv_bfloat162*)hi)[2 * i + 1] = __nv_bfloat162(hz, hw);
    ((__nv_bfloat162*)lo)[2 * i] = __nv_bfloat162(
        __float2bfloat16(v.x - __bfloat162float(hx)),
        __float2bfloat16(v.y - __bfloat162float(hy)));
    ((__nv_bfloat162*)lo)[2 * i + 1] = __nv_bfloat162(
        __float2bfloat16(v.z - __bfloat162float(hz)),
        __float2bfloat16(v.w - __bfloat162float(hw)));
}

// ===========================================================================
// Pipelined bf16 split GEMM (from R3, known-good): C = (Ahi+Alo)@(Bhi+Blo)+bias
// ===========================================================================
#define GBM 128
#define GBN 128
#define GBK 32
#define ASTR 40
#define BSTR 136
#define OFF_AHI 0
#define OFF_ALO 10240
#define OFF_BHI 20480
#define OFF_BLO 29184
#define STAGE_BYTES 37888
#define GEMM_SMEM (2*STAGE_BYTES)

__device__ __forceinline__ void cpasync16(uint32_t dst, const void* src) {
    asm volatile("cp.async.cg.shared.global [%0], [%1], 16;" :: "r"(dst), "l"(src));
}
__device__ __forceinline__ void ldsm4(uint32_t r[4], uint32_t addr) {
    asm volatile("ldmatrix.sync.aligned.m8n8.x4.shared.b16 {%0,%1,%2,%3}, [%4];"
                 : "=r"(r[0]), "=r"(r[1]), "=r"(r[2]), "=r"(r[3]) : "r"(addr));
}
__device__ __forceinline__ void ldsm4t(uint32_t r[4], uint32_t addr) {
    asm volatile("ldmatrix.sync.aligned.m8n8.x4.trans.shared.b16 {%0,%1,%2,%3}, [%4];"
                 : "=r"(r[0]), "=r"(r[1]), "=r"(r[2]), "=r"(r[3]) : "r"(addr));
}
__device__ __forceinline__ void mma_bf16(float d[4], const uint32_t a[4],
                                         uint32_t b0, uint32_t b1) {
    asm volatile(
        "mma.sync.aligned.m16n8k16.row.col.f32.bf16.bf16.f32 "
        "{%0,%1,%2,%3}, {%4,%5,%6,%7}, {%8,%9}, {%0,%1,%2,%3};"
        : "+f"(d[0]), "+f"(d[1]), "+f"(d[2]), "+f"(d[3])
        : "r"(a[0]), "r"(a[1]), "r"(a[2]), "r"(a[3]), "r"(b0), "r"(b1));
}

__global__ __launch_bounds__(256, 2)
void bgemm_split(const __nv_bfloat16* __restrict__ Ahi_g, const __nv_bfloat16* __restrict__ Alo_g,
                 const __nv_bfloat16* __restrict__ Bhi_g, const __nv_bfloat16* __restrict__ Blo_g,
                 const float* __restrict__ bias, float* __restrict__ C,
                 int M, int N, int K)
{
    extern __shared__ char gsm[];
    const int tid  = threadIdx.x;
    const int warp = tid >> 5;
    const int lane = tid & 31;
    const int g  = lane >> 2;
    const int tg = lane & 3;

    const int bm = blockIdx.y * GBM;
    const int bn = blockIdx.x * GBN;
    const int warp_m = (warp >> 1) * 32;
    const int warp_n = (warp & 1) * 64;

    const int ar = tid >> 2, ac = (tid & 3) * 8;
    const int br = tid >> 4, bc = (tid & 15) * 8;
    const __nv_bfloat16* aih = Ahi_g + (size_t)(bm + ar) * K + ac;
    const __nv_bfloat16* ail = Alo_g + (size_t)(bm + ar) * K + ac;
    const __nv_bfloat16* bih = Bhi_g + (size_t)br * N + bn + bc;
    const __nv_bfloat16* bil = Blo_g + (size_t)br * N + bn + bc;
    const size_t a64 = (size_t)64 * K;
    const size_t b16 = (size_t)16 * N;

    const uint32_t smb = (uint32_t)__cvta_generic_to_shared(gsm);
    const uint32_t dA  = (uint32_t)(ar * ASTR + ac) * 2;
    const uint32_t dA2 = (uint32_t)((ar + 64) * ASTR + ac) * 2;
    const uint32_t dB  = (uint32_t)(br * BSTR + bc) * 2;
    const uint32_t dB2 = (uint32_t)((br + 16) * BSTR + bc) * 2;

    float acc[2][8][4];
    #pragma unroll
    for (int mt = 0; mt < 2; mt++)
        #pragma unroll
        for (int nt = 0; nt < 8; nt++)
            #pragma unroll
            for (int i = 0; i < 4; i++) acc[mt][nt][i] = 0.f;

    const int NK = K / GBK;

    #define ISSUE_STAGE(s, kit) do {                                         \
        uint32_t so = smb + (uint32_t)(s) * STAGE_BYTES;                     \
        size_t ka = (size_t)(kit) * GBK;                                     \
        size_t kb = (size_t)(kit) * GBK * (size_t)N;                         \
        cpasync16(so + OFF_AHI + dA,  aih + ka);                             \
        cpasync16(so + OFF_AHI + dA2, aih + a64 + ka);                       \
        cpasync16(so + OFF_ALO + dA,  ail + ka);                             \
        cpasync16(so + OFF_ALO + dA2, ail + a64 + ka);                       \
        cpasync16(so + OFF_BHI + dB,  bih + kb);                             \
        cpasync16(so + OFF_BHI + dB2, bih + b16 + kb);                       \
        cpasync16(so + OFF_BLO + dB,  bil + kb);                             \
        cpasync16(so + OFF_BLO + dB2, bil + b16 + kb);                       \
        asm volatile("cp.async.commit_group;");                              \
    } while (0)

    ISSUE_STAGE(0, 0);

    const int a_r = lane & 15;
    const int a_c = (lane >> 4) * 8;

    for (int it = 0; it < NK; it++) {
        if (it + 1 < NK) {
            ISSUE_STAGE((it + 1) & 1, it + 1);
            asm volatile("cp.async.wait_group 1;");
        } else {
            asm volatile("cp.async.wait_group 0;");
        }
        __syncthreads();

        const uint32_t sb = smb + (uint32_t)(it & 1) * STAGE_BYTES;
        #pragma unroll
        for (int ks = 0; ks < 2; ks++) {
            const int kk = ks * 16;
            uint32_t ah[2][4], al[2][4];
            #pragma unroll
            for (int mt = 0; mt < 2; mt++) {
                uint32_t off = (uint32_t)((warp_m + mt * 16 + a_r) * ASTR + kk + a_c) * 2;
                ldsm4(ah[mt], sb + OFF_AHI + off);
                ldsm4(al[mt], sb + OFF_ALO + off);
            }
            #pragma unroll
            for (int np = 0; np < 4; np++) {
                uint32_t bh[4], bl[4];
                uint32_t off = (uint32_t)((kk + a_r) * BSTR + warp_n + np * 16 + a_c) * 2;
                ldsm4t(bh, sb + OFF_BHI + off);
                ldsm4t(bl, sb + OFF_BLO + off);
                #pragma unroll
                for (int half = 0; half < 2; half++) {
                    const int nt = np * 2 + half;
                    uint32_t b0h = bh[half * 2], b1h = bh[half * 2 + 1];
                    uint32_t b0l = bl[half * 2], b1l = bl[half * 2 + 1];
                    #pragma unroll
                    for (int mt = 0; mt < 2; mt++) {
                        mma_bf16(acc[mt][nt], ah[mt], b0h, b1h);
                        mma_bf16(acc[mt][nt], ah[mt], b0l, b1l);
                        mma_bf16(acc[mt][nt], al[mt], b0h, b1h);
                    }
                }
            }
        }
        __syncthreads();
    }

    #pragma unroll
    for (int nt = 0; nt < 8; nt++) {
        const int col = bn + warp_n + nt * 8 + 2 * tg;
        const float2 bs = *(const float2*)&bias[col];
        #pragma unroll
        for (int mt = 0; mt < 2; mt++) {
            const int row0 = bm + warp_m + mt * 16 + g;
            float2 o0 = make_float2(acc[mt][nt][0] + bs.x, acc[mt][nt][1] + bs.y);
            float2 o1 = make_float2(acc[mt][nt][2] + bs.x, acc[mt][nt][3] + bs.y);
            *(float2*)&C[(size_t)row0 * N + col]       = o0;
            *(float2*)&C[(size_t)(row0 + 8) * N + col] = o1;
        }
    }
    #undef ISSUE_STAGE
}

// ===========================================================================
// Flash attention, tf32 mma (raw fp32 operands -> hw tf32 truncation), causal.
// 256 threads (8 warps), BQ=128, KV tiles 64, 3-stage cp.async pipeline.
// ===========================================================================
#define AT_BQ    128
#define AT_BKV   64
#define KSTR     68                      // words/row: 16B-aligned, conflict-free
#define AT_STG_W (2 * AT_BKV * KSTR)     // K+V words per stage = 8704
#define AT_SMEM  (3 * AT_STG_W * 4)      // 104448 bytes
#define SCALE    0.125f

__device__ __forceinline__ void mma_tf32(float d[4], const uint32_t a[4],
                                         uint32_t b0, uint32_t b1) {
    asm volatile(
        "mma.sync.aligned.m16n8k8.row.col.f32.tf32.tf32.f32 "
        "{%0,%1,%2,%3}, {%4,%5,%6,%7}, {%8,%9}, {%0,%1,%2,%3};"
        : "+f"(d[0]), "+f"(d[1]), "+f"(d[2]), "+f"(d[3])
        : "r"(a[0]), "r"(a[1]), "r"(a[2]), "r"(a[3]), "r"(b0), "r"(b1));
}

__global__ __launch_bounds__(256)
void attn_tc(const float* __restrict__ qkv,
             __nv_bfloat16* __restrict__ yhi, __nv_bfloat16* __restrict__ ylo)
{
    extern __shared__ float asm_pool[];

    const int b = blockIdx.z, h = blockIdx.y;
    const int qtile = gridDim.x - 1 - blockIdx.x;   // heavy tiles first
    const int q0 = qtile * AT_BQ;
    const int tid  = threadIdx.x;
    const int warp = tid >> 5;
    const int lane = tid & 31;
    const int g  = lane >> 2;
    const int tg = lane & 3;

    const int qi0 = q0 + warp * 16 + g;
    const int qi1 = qi0 + 8;
    const int w_qmax = q0 + warp * 16 + 15;
    const int w_qmin = q0 + warp * 16;

    // ---- Q A-frags straight from gmem (raw fp32 bits) ----
    uint32_t Aq[8][4];
    {
        const float* qg = qkv + (size_t)(b * Tn + qi0) * QKV_N + h * HDn;
        const float* qg8 = qg + (size_t)8 * QKV_N;
        #pragma unroll
        for (int k = 0; k < 8; k++) {
            Aq[k][0] = __float_as_uint(qg [k * 8 + tg]);
            Aq[k][1] = __float_as_uint(qg8[k * 8 + tg]);
            Aq[k][2] = __float_as_uint(qg [k * 8 + tg + 4]);
            Aq[k][3] = __float_as_uint(qg8[k * 8 + tg + 4]);
        }
    }

    const uint32_t smb = (uint32_t)__cvta_generic_to_shared(asm_pool);

    // per-thread cp.async geometry: 4 rows of K + 4 rows of V per stage
    int rr[4]; uint32_t dw[4];
    #pragma unroll
    for (int i = 0; i < 4; i++) {
        int f = i * 256 + tid;          // 0..1023
        rr[i] = f >> 4;                 // kv row 0..63
        dw[i] = (uint32_t)(rr[i] * KSTR + (f & 15) * 4) * 4;   // byte offset
    }
    const float* kbase = qkv + (size_t)b * Tn * QKV_N +     Cn + h * HDn;
    const float* vbase = qkv + (size_t)b * Tn * QKV_N + 2 * Cn + h * HDn;

    const int NT = (q0 + AT_BQ) / AT_BKV;   // >= 2

    #define AT_ISSUE(tile, s) do {                                            \
        const uint32_t _so = smb + (uint32_t)(s) * (AT_STG_W * 4);            \
        const int _kt = (tile) * AT_BKV;                                      \
        _Pragma("unroll")                                                     \
        for (int _i = 0; _i < 4; _i++) {                                      \
            const size_t _ro = (size_t)(_kt + rr[_i]) * QKV_N;                \
            const int _cw = dw[_i];                                           \
            cpasync16(_so + _cw, kbase + _ro + ((_cw >> 2) % KSTR));          \
            cpasync16(_so + AT_BKV * KSTR * 4 + _cw,                          \
                      vbase + _ro + ((_cw >> 2) % KSTR));                     \
        }                                                                     \
        asm volatile("cp.async.commit_group;");                               \
    } while (0)

    AT_ISSUE(0, 0);
    AT_ISSUE(1, 1);

    float O[8][4];
    #pragma unroll
    for (int nt = 0; nt < 8; nt++)
        #pragma unroll
        for (int i = 0; i < 4; i++) O[nt][i] = 0.f;

    float m0 = -INFINITY, m1 = -INFINITY;
    float l0 = 0.f, l1 = 0.f;

    for (int it = 0; it < NT; it++) {
        asm volatile("cp.async.wait_group 1;");
        __syncthreads();
        if (it + 2 < NT) AT_ISSUE(it + 2, (it + 2) % 3);

        const int kt = it * AT_BKV;
        const float* Ks = asm_pool + (it % 3) * AT_STG_W;
        const float* Vs = Ks + AT_BKV * KSTR;

        if (kt <= w_qmax) {
            // ---- S = Q @ K^T ----
            float S[8][4];
            #pragma unroll
            for (int nt = 0; nt < 8; nt++) {
                S[nt][0] = S[nt][1] = S[nt][2] = S[nt][3] = 0.f;
                #pragma unroll
                for (int k = 0; k < 8; k++) {
                    uint32_t b0 = __float_as_uint(Ks[(nt * 8 + g) * KSTR + k * 8 + tg    ]);
                    uint32_t b1 = __float_as_uint(Ks[(nt * 8 + g) * KSTR + k * 8 + tg + 4]);
                    mma_tf32(S[nt], Aq[k], b0, b1);
                }
            }

            const bool need_mask = (kt + AT_BKV - 1 > w_qmin);
            #pragma unroll
            for (int nt = 0; nt < 8; nt++) {
                int j0 = kt + nt * 8 + 2 * tg;
                int j1 = j0 + 1;
                S[nt][0] *= SCALE; S[nt][1] *= SCALE;
                S[nt][2] *= SCALE; S[nt][3] *= SCALE;
                if (need_mask) {
                    if (j0 > qi0) S[nt][0] = -INFINITY;
                    if (j1 > qi0) S[nt][1] = -INFINITY;
                    if (j0 > qi1) S[nt][2] = -INFINITY;
                    if (j1 > qi1) S[nt][3] = -INFINITY;
                }
            }

            // ---- online softmax ----
            float mc0 = -INFINITY, mc1 = -INFINITY;
            #pragma unroll
            for (int nt = 0; nt < 8; nt++) {
                mc0 = fmaxf(mc0, fmaxf(S[nt][0], S[nt][1]));
                mc1 = fmaxf(mc1, fmaxf(S[nt][2], S[nt][3]));
            }
            mc0 = fmaxf(mc0, __shfl_xor_sync(0xffffffffu, mc0, 1));
            mc0 = fmaxf(mc0, __shfl_xor_sync(0xffffffffu, mc0, 2));
            mc1 = fmaxf(mc1, __shfl_xor_sync(0xffffffffu, mc1, 1));
            mc1 = fmaxf(mc1, __shfl_xor_sync(0xffffffffu, mc1, 2));

            float mn0 = fmaxf(m0, mc0);
            float mn1 = fmaxf(m1, mc1);
            float corr0 = __expf(m0 - mn0);
            float corr1 = __expf(m1 - mn1);
            m0 = mn0; m1 = mn1;

            float ps0 = 0.f, ps1 = 0.f;
            #pragma unroll
            for (int nt = 0; nt < 8; nt++) {
                S[nt][0] = __expf(S[nt][0] - mn0);
                S[nt][1] = __expf(S[nt][1] - mn0);
                S[nt][2] = __expf(S[nt][2] - mn1);
                S[nt][3] = __expf(S[nt][3] - mn1);
                ps0 += S[nt][0] + S[nt][1];
                ps1 += S[nt][2] + S[nt][3];
            }
            ps0 += __shfl_xor_sync(0xffffffffu, ps0, 1);
            ps0 += __shfl_xor_sync(0xffffffffu, ps0, 2);
            ps1 += __shfl_xor_sync(0xffffffffu, ps1, 1);
            ps1 += __shfl_xor_sync(0xffffffffu, ps1, 2);
            l0 = l0 * corr0 + ps0;
            l1 = l1 * corr1 + ps1;

            #pragma unroll
            for (int nt = 0; nt < 8; nt++) {
                O[nt][0] *= corr0; O[nt][1] *= corr0;
                O[nt][2] *= corr1; O[nt][3] *= corr1;
            }

            // ---- O += P @ V ----
            const int src_lo = (lane & ~3) | (tg >> 1);
            const int src_hi = src_lo + 2;
            const bool odd = (tg & 1);
            #pragma unroll
            for (int kk = 0; kk < 8; kk++) {
                float p0 = S[kk][0], p1 = S[kk][1], p2 = S[kk][2], p3 = S[kk][3];
                float u, v;
                uint32_t Ap[4];
                u = __shfl_sync(0xffffffffu, p0, src_lo);
                v = __shfl_sync(0xffffffffu, p1, src_lo);
                Ap[0] = __float_as_uint(odd ? v : u);
                u = __shfl_sync(0xffffffffu, p2, src_lo);
                v = __shfl_sync(0xffffffffu, p3, src_lo);
                Ap[1] = __float_as_uint(odd ? v : u);
                u = __shfl_sync(0xffffffffu, p0, src_hi);
                v = __shfl_sync(0xffffffffu, p1, src_hi);
                Ap[2] = __float_as_uint(odd ? v : u);
                u = __shfl_sync(0xffffffffu, p2, src_hi);
                v = __shfl_sync(0xffffffffu, p3, src_hi);
                Ap[3] = __float_as_uint(odd ? v : u);

                #pragma unroll
                for (int dd = 0; dd < 8; dd++) {
                    uint32_t b0 = __float_as_uint(Vs[(kk * 8 + tg    ) * KSTR + dd * 8 + g]);
                    uint32_t b1 = __float_as_uint(Vs[(kk * 8 + tg + 4) * KSTR + dd * 8 + g]);
                    mma_tf32(O[dd], Ap, b0, b1);
                }
            }
        }
        __syncthreads();
    }

    // ---- finalize: divide by l, split to bf16 hi/lo, store ----
    const float inv0 = 1.f / l0;
    const float inv1 = 1.f / l1;
    const size_t row0 = (size_t)(b * Tn + qi0) * Cn + h * HDn;
    const size_t row1 = (size_t)(b * Tn + qi1) * Cn + h * HDn;
    #pragma unroll
    for (int nt = 0; nt < 8; nt++) {
        int c = nt * 8 + 2 * tg;
        float v00 = O[nt][0] * inv0, v01 = O[nt][1] * inv0;
        float v10 = O[nt][2] * inv1, v11 = O[nt][3] * inv1;
        __nv_bfloat16 h00 = __float2bfloat16(v00), h01 = __float2bfloat16(v01);
        __nv_bfloat16 h10 = __float2bfloat16(v10), h11 = __float2bfloat16(v11);
        *(__nv_bfloat162*)&yhi[row0 + c] = __nv_bfloat162(h00, h01);
        *(__nv_bfloat162*)&yhi[row1 + c] = __nv_bfloat162(h10, h11);
        *(__nv_bfloat162*)&ylo[row0 + c] = __nv_bfloat162(
            __float2bfloat16(v00 - __bfloat162float(h00)),
            __float2bfloat16(v01 - __bfloat162float(h01)));
        *(__nv_bfloat162*)&ylo[row1 + c] = __nv_bfloat162(
            __float2bfloat16(v10 - __bfloat162float(h10)),
            __float2bfloat16(v11 - __bfloat162float(h11)));
    }
    #undef AT_ISSUE
}

// ---------------------------------------------------------------------------
// Launch
// ---------------------------------------------------------------------------
extern "C" void kernel_launch(void* const* d_in, const int* in_sizes, int n_in,
                              void* d_out, int out_size)
{
    const float* x      = (const float*)d_in[0];
    const float* w_attn = (const float*)d_in[1];
    const float* b_attn = (const float*)d_in[2];
    const float* w_proj = (const float*)d_in[3];
    const float* b_proj = (const float*)d_in[4];
    float* out = (float*)d_out;

    float* qkv_ptr; __nv_bfloat16 *xhi, *xlo, *wahi, *walo, *wphi, *wplo, *yhi, *ylo;
    cudaGetSymbolAddress((void**)&qkv_ptr, g_qkv);
    cudaGetSymbolAddress((void**)&xhi,  g_xhi);
    cudaGetSymbolAddress((void**)&xlo,  g_xlo);
    cudaGetSymbolAddress((void**)&wahi, g_wahi);
    cudaGetSymbolAddress((void**)&walo, g_walo);
    cudaGetSymbolAddress((void**)&wphi, g_wphi);
    cudaGetSymbolAddress((void**)&wplo, g_wplo);
    cudaGetSymbolAddress((void**)&yhi,  g_yhi);
    cudaGetSymbolAddress((void**)&ylo,  g_ylo);

    cudaFuncSetAttribute(bgemm_split, cudaFuncAttributeMaxDynamicSharedMemorySize, GEMM_SMEM);
    cudaFuncSetAttribute(attn_tc, cudaFuncAttributeMaxDynamicSharedMemorySize, AT_SMEM);

    // 0) split inputs into bf16 hi/lo
    {
        int n4;
        n4 = (Mrows * Cn) / 4;
        split_kernel<<<(n4 + 255) / 256, 256>>>(x, xhi, xlo, n4);
        n4 = (Cn * QKV_N) / 4;
        split_kernel<<<(n4 + 255) / 256, 256>>>(w_attn, wahi, walo, n4);
        n4 = (Cn * Cn) / 4;
        split_kernel<<<(n4 + 255) / 256, 256>>>(w_proj, wphi, wplo, n4);
    }
    // 1) QKV projection
    {
        dim3 grid(QKV_N / GBN, Mrows / GBM);
        bgemm_split<<<grid, 256, GEMM_SMEM>>>(xhi, xlo, wahi, walo, b_attn,
                                              qkv_ptr, Mrows, QKV_N, Cn);
    }
    // 2) Causal attention (tf32 tensor cores, cp.async pipelined)
    {
        dim3 grid(Tn / AT_BQ, Hn, Bn);
        attn_tc<<<grid, 256, AT_SMEM>>>(qkv_ptr, yhi, ylo);
    }
    // 3) Output projection
    {
        dim3 grid(Cn / GBN, Mrows / GBM);
        bgemm_split<<<grid, 256, GEMM_SMEM>>>(yhi, ylo, wphi, wplo, b_proj,
                                              out, Mrows, Cn, Cn);
    }
}